// round 7
// baseline (speedup 1.0000x reference)
#include <cuda_runtime.h>

#define NUM_SEGMENTS 512
#define THREADS 1024
#define ROWG (THREADS / 16)   // 64 row-groups, 16 float4 lanes per 64-float row

__device__ __forceinline__ int lower_bound_i32(const int* __restrict__ b, int n, int v) {
    int lo = 0, hi = n;
    while (lo < hi) {
        int mid = (lo + hi) >> 1;
        if (b[mid] < v) lo = mid + 1; else hi = mid;
    }
    return lo;
}

extern __shared__ float4 sm4[];   // 16 KB used; 128 KB requested to force 1 CTA/SM

__global__ __launch_bounds__(THREADS, 1)
void pairnorm_kernel(const float4* __restrict__ x4,
                     const int* __restrict__ batch,   // int32! (JAX x64 disabled)
                     float4* __restrict__ out4,
                     int N)
{
    __shared__ float s_ssq[THREADS / 32];
    __shared__ float s_inv;
    __shared__ int s_lo, s_hi;

    const int tid = threadIdx.x;
    const int seg = (int)blockIdx.x;

    if (tid == 0)  s_lo = lower_bound_i32(batch, N, seg);
    if (tid == 32) s_hi = lower_bound_i32(batch, N, seg + 1);
    __syncthreads();
    const int lo = s_lo, hi = s_hi;

    const int lane16 = tid & 15;   // which float4 of the row
    const int rg     = tid >> 4;   // row group 0..63

    // ---- Pass 1: segment sum[64] and sum of squared norms ----
    float4 acc = make_float4(0.f, 0.f, 0.f, 0.f);
    float ssq = 0.f;
    #pragma unroll 8
    for (int r = lo + rg; r < hi; r += ROWG) {
        float4 v = x4[(size_t)r * 16 + lane16];
        acc.x += v.x; acc.y += v.y; acc.z += v.z; acc.w += v.w;
        ssq += v.x * v.x + v.y * v.y + v.z * v.z + v.w * v.w;
    }
    sm4[rg * 16 + lane16] = acc;

    // warp-reduce ssq, one partial per warp
    #pragma unroll
    for (int off = 16; off > 0; off >>= 1)
        ssq += __shfl_xor_sync(0xffffffffu, ssq, off);
    if ((tid & 31) == 0) s_ssq[tid >> 5] = ssq;
    __syncthreads();

    // tree-reduce 64 row-group partials down to row 0 (the 64-wide sum)
    #pragma unroll
    for (int off = ROWG / 2; off >= 1; off >>= 1) {
        if (rg < off) {
            float4 a = sm4[rg * 16 + lane16];
            float4 b = sm4[(rg + off) * 16 + lane16];
            a.x += b.x; a.y += b.y; a.z += b.z; a.w += b.w;
            sm4[rg * 16 + lane16] = a;
        }
        __syncthreads();
    }

    // finalize: mean (kept in sm4[0..15]) and 1/sqrt(mean centered sq-norm)
    if (tid == 0) {
        float tot = 0.f;
        #pragma unroll
        for (int w = 0; w < THREADS / 32; w++) tot += s_ssq[w];
        const int cnt = hi - lo;
        const float invc = 1.f / (float)(cnt > 0 ? cnt : 1);
        float msq = 0.f;
        #pragma unroll
        for (int i = 0; i < 16; i++) {
            float4 m = sm4[i];
            m.x *= invc; m.y *= invc; m.z *= invc; m.w *= invc;
            sm4[i] = m;
            msq += m.x * m.x + m.y * m.y + m.z * m.z + m.w * m.w;
        }
        // sum||x-m||^2 / cnt = sumsq/cnt - ||m||^2
        float var = fmaxf(tot * invc - msq, 0.f);
        s_inv = rsqrtf(var);
    }
    __syncthreads();

    const float4 mean = sm4[lane16];
    const float inv = s_inv;

    // ---- Pass 2: re-read (L2-resident) and write normalized output ----
    #pragma unroll 8
    for (int r = lo + rg; r < hi; r += ROWG) {
        float4 v = x4[(size_t)r * 16 + lane16];
        float4 o;
        o.x = (v.x - mean.x) * inv;
        o.y = (v.y - mean.y) * inv;
        o.z = (v.z - mean.z) * inv;
        o.w = (v.w - mean.w) * inv;
        out4[(size_t)r * 16 + lane16] = o;
    }
}

extern "C" void kernel_launch(void* const* d_in, const int* in_sizes, int n_in,
                              void* d_out, int out_size)
{
    const float4* x4    = (const float4*)d_in[0];
    const int*    batch = (const int*)d_in[1];     // int32 per metadata (JAX x64 off)
    float4*       out4  = (float4*)d_out;
    const int N = in_sizes[1];   // 1,000,000 rows; D = 64 fixed

    // 128 KB dynamic smem: two CTAs would exceed the 227 KB/SM cap, forcing
    // 1 CTA/SM so the resident pass-1 working set (148 x ~500 KB = 74 MB)
    // stays inside L2 for the pass-2 re-read.
    static const int kSmem = 128 * 1024;
    cudaFuncSetAttribute(pairnorm_kernel, cudaFuncAttributeMaxDynamicSharedMemorySize, kSmem);
    pairnorm_kernel<<<NUM_SEGMENTS, THREADS, kSmem>>>(x4, batch, out4, N);
}